// round 8
// baseline (speedup 1.0000x reference)
#include <cuda_runtime.h>
#include <cuda_bf16.h>
#include <stdint.h>

// Problem dims (fixed by the dataset)
#define NODES 65536
#define DIM   256
#define NEXP  8
#define HDIM  1024

// -------------------- device scratch (static allocation only) --------------------
static __device__ __align__(256) __nv_bfloat16 g_Hb [(size_t)NODES * DIM];          // H in bf16
static __device__ __align__(256) __nv_bfloat16 g_W1t[(size_t)NEXP * HDIM * DIM];    // [e][h][d] (k-contig)
static __device__ __align__(256) __nv_bfloat16 g_W2t[(size_t)NEXP * DIM * HDIM];    // [e][d][h] (k-contig)
static __device__ __align__(256) float         g_gate[(size_t)NODES * NEXP];        // softmax gate weights

// -------------------- helpers --------------------
__device__ __forceinline__ void cp_async16(void* dst_smem, const void* src_gmem) {
    unsigned s = (unsigned)__cvta_generic_to_shared(dst_smem);
    asm volatile("cp.async.cg.shared.global [%0], [%1], 16;\n" :: "r"(s), "l"(src_gmem) : "memory");
}
__device__ __forceinline__ void cp_commit() {
    asm volatile("cp.async.commit_group;\n" ::: "memory");
}

__device__ __forceinline__ void mma16816(float c[4], const uint32_t a[4], const uint32_t b[2]) {
    asm volatile(
        "mma.sync.aligned.m16n8k16.row.col.f32.bf16.bf16.f32 "
        "{%0,%1,%2,%3}, {%4,%5,%6,%7}, {%8,%9}, {%0,%1,%2,%3};\n"
        : "+f"(c[0]), "+f"(c[1]), "+f"(c[2]), "+f"(c[3])
        : "r"(a[0]), "r"(a[1]), "r"(a[2]), "r"(a[3]), "r"(b[0]), "r"(b[1]));
}

// -------------------- prep kernels --------------------
__global__ void k_cvt_H(const float* __restrict__ H) {
    size_t i = (size_t)blockIdx.x * 256 + threadIdx.x;   // grid covers exactly NODES*DIM
    g_Hb[i] = __float2bfloat16(H[i]);
}

// W1: [e][d=256][h=1024] -> W1t: [e][h][d]  (k=d contiguous)
__global__ void k_cvt_W1(const float* __restrict__ W1) {
    size_t i = (size_t)blockIdx.x * 256 + threadIdx.x;   // 2097152 elems
    int k = (int)(i & 255);
    int n = (int)((i >> 8) & 1023);
    int e = (int)(i >> 18);
    g_W1t[i] = __float2bfloat16(W1[((size_t)e * 256 + k) * 1024 + n]);
}

// W2: [e][h=1024][d=256] -> W2t: [e][d][h]  (k=h contiguous)
__global__ void k_cvt_W2(const float* __restrict__ W2) {
    size_t i = (size_t)blockIdx.x * 256 + threadIdx.x;   // 2097152 elems
    int h = (int)(i & 1023);
    int d = (int)((i >> 10) & 255);
    int e = (int)(i >> 18);
    g_W2t[i] = __float2bfloat16(W2[((size_t)e * 1024 + h) * 256 + d]);
}

// Gate: softmax(H @ gate_w + gate_b) per node. One warp per node.
__global__ void k_gate(const float* __restrict__ H, const float* __restrict__ gw,
                       const float* __restrict__ gb) {
    __shared__ float gws[256 * 9];             // padded stride 9 -> conflict free
    int tid  = threadIdx.x;
    int lane = tid & 31, wid = tid >> 5;
    for (int i = tid; i < 2048; i += 256) {
        int d = i >> 3, e = i & 7;
        gws[d * 9 + e] = gw[i];
    }
    __syncthreads();

    size_t node = (size_t)blockIdx.x * 8 + wid;
    float acc[8];
#pragma unroll
    for (int e = 0; e < 8; ++e) acc[e] = 0.f;
#pragma unroll
    for (int i = 0; i < 8; ++i) {
        int d = lane + 32 * i;
        float hv = H[node * 256 + d];
#pragma unroll
        for (int e = 0; e < 8; ++e) acc[e] += hv * gws[d * 9 + e];
    }
#pragma unroll
    for (int off = 16; off > 0; off >>= 1) {
#pragma unroll
        for (int e = 0; e < 8; ++e) acc[e] += __shfl_xor_sync(0xFFFFFFFFu, acc[e], off);
    }
    float l[8];
#pragma unroll
    for (int e = 0; e < 8; ++e) l[e] = acc[e] + gb[e];
    float m = l[0];
#pragma unroll
    for (int e = 1; e < 8; ++e) m = fmaxf(m, l[e]);
    float ex[8], s = 0.f;
#pragma unroll
    for (int e = 0; e < 8; ++e) { ex[e] = expf(l[e] - m); s += ex[e]; }
    float inv = 1.f / s;
    if (lane < 8) {
        float v = 0.f;
#pragma unroll
        for (int e = 0; e < 8; ++e) if (lane == e) v = ex[e];
        g_gate[node * 8 + lane] = v * inv;
    }
}

// -------------------- main fused kernel --------------------
// Tile: 64 nodes per CTA, 256 threads (8 warps as 2(m) x 4(n)).
// Per expert e, per Hd-chunk c (128 wide):
//   h = relu(Hs @ W1[e,:,c*128:+128] + b1) * gate_w[:,e]   (bf16 to smem)
//   y += h @ W2[e,c*128:+128,:]                            (fp32 regs, persists across all e,c)
// Epilogue: x = H + y + sum_e w_e*b2_e; LayerNorm; write out.

// smem strides (elements), all chosen so (stride_words mod 32) == 4 -> conflict-free frags
#define SH   264   // Hs   [64][264] bf16
#define SW1  264   // W1s  [128][264] bf16
#define SHH  136   // hS   [64][136] bf16
#define SW2  136   // W2s  [256][136] bf16
#define SX   260   // xS   [64][260] fp32 (aliases W1s)

#define OFF_HS   0
#define OFF_W1S  33792
#define OFF_HSH  101376
#define OFF_W2S  118784
#define OFF_GATE 188416
#define OFF_B2   190464
#define OFF_B1   198656
#define SMEM_BYTES 199168

__global__ void __launch_bounds__(256, 1)
k_main(const float* __restrict__ H, const float* __restrict__ b1g,
       const float* __restrict__ b2g, const float* __restrict__ gamma,
       const float* __restrict__ beta, float* __restrict__ out)
{
    extern __shared__ char smem_raw[];
    __nv_bfloat16* Hs   = reinterpret_cast<__nv_bfloat16*>(smem_raw + OFF_HS);
    __nv_bfloat16* W1s  = reinterpret_cast<__nv_bfloat16*>(smem_raw + OFF_W1S);
    __nv_bfloat16* hS   = reinterpret_cast<__nv_bfloat16*>(smem_raw + OFF_HSH);
    __nv_bfloat16* W2s  = reinterpret_cast<__nv_bfloat16*>(smem_raw + OFF_W2S);
    float*         gate_s = reinterpret_cast<float*>(smem_raw + OFF_GATE);   // [64][8]
    float*         b2s    = reinterpret_cast<float*>(smem_raw + OFF_B2);     // [8][256]
    float*         b1s    = reinterpret_cast<float*>(smem_raw + OFF_B1);     // [128]

    const int tid   = threadIdx.x;
    const int node0 = blockIdx.x * 64;
    const int lane  = tid & 31, wid = tid >> 5;
    const int wm = wid & 1, wn = wid >> 1;
    const int m0 = wm * 32;
    const int lq = lane >> 2, lr = lane & 3;

    // ---- async copy Hs tile (64 x 256 bf16) ----
    {
        const char* src = (const char*)(g_Hb + (size_t)node0 * 256);
#pragma unroll
        for (int i = 0; i < 8; ++i) {
            int u = tid + i * 256;      // 2048 x 16B
            int r = u >> 5, o = u & 31;
            cp_async16((char*)Hs + r * 528 + o * 16, src + (size_t)r * 512 + o * 16);
        }
    }
    // ---- prefetch W1 chunk (e=0,c=0): 128 rows x 512B ----
    {
        const char* src = (const char*)g_W1t;
#pragma unroll
        for (int i = 0; i < 16; ++i) {
            int u = tid + i * 256;      // 4096 x 16B
            int n = u >> 5, o = u & 31;
            cp_async16((char*)W1s + n * 528 + o * 16, src + (size_t)n * 512 + o * 16);
        }
    }
    cp_commit();   // group: {Hs, W1(0,0)}

    // gate weights + b2 staged once
    for (int i = tid; i < 64 * 8; i += 256) gate_s[i] = g_gate[(size_t)node0 * 8 + i];
    for (int i = tid; i < 8 * 256; i += 256) b2s[i] = b2g[i];

    float y[2][8][4];
#pragma unroll
    for (int mi = 0; mi < 2; ++mi)
#pragma unroll
        for (int ni = 0; ni < 8; ++ni)
#pragma unroll
            for (int q = 0; q < 4; ++q) y[mi][ni][q] = 0.f;

    for (int cc = 0; cc < 64; ++cc) {
        const int e = cc >> 3, c = cc & 7;

        // prefetch W2 chunk (e,c): 256 rows x 256B (strided in global)
        {
            const char* src = (const char*)(g_W2t + ((size_t)e * 256) * 1024 + c * 128);
#pragma unroll
            for (int i = 0; i < 16; ++i) {
                int u = tid + i * 256;      // 4096 x 16B
                int n = u >> 4, o = u & 15;
                cp_async16((char*)W2s + n * 272 + o * 16, src + (size_t)n * 2048 + o * 16);
            }
            cp_commit();
        }
        if (tid < 128) b1s[tid] = b1g[e * 1024 + c * 128 + tid];

        // wait for W1 chunk (older group); W2 may still be in flight
        asm volatile("cp.async.wait_group 1;\n" ::: "memory");
        __syncthreads();

        // ---------------- GEMM1: h_chunk[64x128] = Hs[64x256] @ W1chunk ----------------
        float a1[2][4][4];
#pragma unroll
        for (int mi = 0; mi < 2; ++mi)
#pragma unroll
            for (int ni = 0; ni < 4; ++ni)
#pragma unroll
                for (int q = 0; q < 4; ++q) a1[mi][ni][q] = 0.f;

#pragma unroll
        for (int kk = 0; kk < 16; ++kk) {
            const int k0 = kk * 16;
            uint32_t af[2][4];
#pragma unroll
            for (int mi = 0; mi < 2; ++mi) {
                const __nv_bfloat16* p = Hs + (m0 + mi * 16 + lq) * SH + k0 + lr * 2;
                af[mi][0] = *reinterpret_cast<const uint32_t*>(p);
                af[mi][1] = *reinterpret_cast<const uint32_t*>(p + 8 * SH);
                af[mi][2] = *reinterpret_cast<const uint32_t*>(p + 8);
                af[mi][3] = *reinterpret_cast<const uint32_t*>(p + 8 * SH + 8);
            }
#pragma unroll
            for (int ni = 0; ni < 4; ++ni) {
                const __nv_bfloat16* p = W1s + (wn * 32 + ni * 8 + lq) * SW1 + k0 + lr * 2;
                uint32_t bv[2];
                bv[0] = *reinterpret_cast<const uint32_t*>(p);
                bv[1] = *reinterpret_cast<const uint32_t*>(p + 8);
#pragma unroll
                for (int mi = 0; mi < 2; ++mi) mma16816(a1[mi][ni], af[mi], bv);
            }
        }

        // epilogue1: +b1, relu, * gate weight, -> bf16 smem
#pragma unroll
        for (int mi = 0; mi < 2; ++mi) {
            const int r0 = m0 + mi * 16 + lq, r1 = r0 + 8;
            const float w0 = gate_s[r0 * 8 + e];
            const float w1 = gate_s[r1 * 8 + e];
#pragma unroll
            for (int ni = 0; ni < 4; ++ni) {
                const int cl = wn * 32 + ni * 8 + lr * 2;
                const float bb0 = b1s[cl], bb1 = b1s[cl + 1];
                float v00 = fmaxf(a1[mi][ni][0] + bb0, 0.f) * w0;
                float v01 = fmaxf(a1[mi][ni][1] + bb1, 0.f) * w0;
                float v10 = fmaxf(a1[mi][ni][2] + bb0, 0.f) * w1;
                float v11 = fmaxf(a1[mi][ni][3] + bb1, 0.f) * w1;
                *reinterpret_cast<__nv_bfloat162*>(hS + r0 * SHH + cl) = __floats2bfloat162_rn(v00, v01);
                *reinterpret_cast<__nv_bfloat162*>(hS + r1 * SHH + cl) = __floats2bfloat162_rn(v10, v11);
            }
        }
        __syncthreads();   // hS visible; everyone done reading W1s

        // prefetch next W1 chunk (overlaps GEMM2)
        if (cc + 1 < 64) {
            const int e2 = (cc + 1) >> 3, c2 = (cc + 1) & 7;
            const char* src = (const char*)(g_W1t + ((size_t)e2 * 1024 + c2 * 128) * 256);
#pragma unroll
            for (int i = 0; i < 16; ++i) {
                int u = tid + i * 256;
                int n = u >> 5, o = u & 31;
                cp_async16((char*)W1s + n * 528 + o * 16, src + (size_t)n * 512 + o * 16);
            }
            cp_commit();
            asm volatile("cp.async.wait_group 1;\n" ::: "memory");   // W2(cur) done
        } else {
            asm volatile("cp.async.wait_group 0;\n" ::: "memory");
        }
        __syncthreads();

        // ---------------- GEMM2: y[64x256] += h_chunk[64x128] @ W2chunk ----------------
#pragma unroll
        for (int kk = 0; kk < 8; ++kk) {
            const int k0 = kk * 16;
            uint32_t af[2][4];
#pragma unroll
            for (int mi = 0; mi < 2; ++mi) {
                const __nv_bfloat16* p = hS + (m0 + mi * 16 + lq) * SHH + k0 + lr * 2;
                af[mi][0] = *reinterpret_cast<const uint32_t*>(p);
                af[mi][1] = *reinterpret_cast<const uint32_t*>(p + 8 * SHH);
                af[mi][2] = *reinterpret_cast<const uint32_t*>(p + 8);
                af[mi][3] = *reinterpret_cast<const uint32_t*>(p + 8 * SHH + 8);
            }
#pragma unroll
            for (int ni = 0; ni < 8; ++ni) {
                const __nv_bfloat16* p = W2s + (wn * 64 + ni * 8 + lq) * SW2 + k0 + lr * 2;
                uint32_t bv[2];
                bv[0] = *reinterpret_cast<const uint32_t*>(p);
                bv[1] = *reinterpret_cast<const uint32_t*>(p + 8);
#pragma unroll
                for (int mi = 0; mi < 2; ++mi) mma16816(y[mi][ni], af[mi], bv);
            }
        }
        __syncthreads();
    }

    // ---------------- final epilogue: residual + gated b2 bias, then LayerNorm ----------------
    float* xS = reinterpret_cast<float*>(smem_raw + OFF_W1S);   // reuse W1s region
#pragma unroll
    for (int mi = 0; mi < 2; ++mi) {
        const int r0 = m0 + mi * 16 + lq, r1 = r0 + 8;
#pragma unroll
        for (int ni = 0; ni < 8; ++ni) {
            const int cc2 = wn * 64 + ni * 8 + lr * 2;
            float bx00 = 0.f, bx01 = 0.f, bx10 = 0.f, bx11 = 0.f;
#pragma unroll
            for (int ee = 0; ee < 8; ++ee) {
                const float w0 = gate_s[r0 * 8 + ee];
                const float w1 = gate_s[r1 * 8 + ee];
                const float2 bb = *reinterpret_cast<const float2*>(&b2s[ee * 256 + cc2]);
                bx00 += w0 * bb.x; bx01 += w0 * bb.y;
                bx10 += w1 * bb.x; bx11 += w1 * bb.y;
            }
            float2 h0 = *reinterpret_cast<const float2*>(H + (size_t)(node0 + r0) * 256 + cc2);
            float2 h1 = *reinterpret_cast<const float2*>(H + (size_t)(node0 + r1) * 256 + cc2);
            float2 x0 = make_float2(h0.x + y[mi][ni][0] + bx00, h0.y + y[mi][ni][1] + bx01);
            float2 x1 = make_float2(h1.x + y[mi][ni][2] + bx10, h1.y + y[mi][ni][3] + bx11);
            *reinterpret_cast<float2*>(&xS[r0 * SX + cc2]) = x0;
            *reinterpret_cast<float2*>(&xS[r1 * SX + cc2]) = x1;
        }
    }
    __syncthreads();

    // LayerNorm: warp w handles rows w*8 .. w*8+7
    for (int rr = 0; rr < 8; ++rr) {
        const int r = wid * 8 + rr;
        float xv[8], s = 0.f, s2 = 0.f;
#pragma unroll
        for (int i = 0; i < 8; ++i) {
            xv[i] = xS[r * SX + lane + 32 * i];
            s += xv[i];
            s2 += xv[i] * xv[i];
        }
#pragma unroll
        for (int off = 16; off > 0; off >>= 1) {
            s  += __shfl_xor_sync(0xFFFFFFFFu, s,  off);
            s2 += __shfl_xor_sync(0xFFFFFFFFu, s2, off);
        }
        const float mu  = s * (1.f / 256.f);
        const float var = s2 * (1.f / 256.f) - mu * mu;
        const float rs  = rsqrtf(var + 1e-5f);
#pragma unroll
        for (int i = 0; i < 8; ++i) {
            const int col = lane + 32 * i;
            out[(size_t)(node0 + r) * 256 + col] = (xv[i] - mu) * rs * gamma[col] + beta[col];
        }
    }
}

// -------------------- launch --------------------
extern "C" void kernel_launch(void* const* d_in, const int* in_sizes, int n_in,
                              void* d_out, int out_size) {
    (void)in_sizes; (void)n_in; (void)out_size;
    const float* H      = (const float*)d_in[0];
    const float* gate_w = (const float*)d_in[1];
    const float* gate_b = (const float*)d_in[2];
    const float* W1     = (const float*)d_in[3];
    const float* b1     = (const float*)d_in[4];
    const float* W2     = (const float*)d_in[5];
    const float* b2     = (const float*)d_in[6];
    const float* gamma  = (const float*)d_in[7];
    const float* beta   = (const float*)d_in[8];
    float* out = (float*)d_out;

    cudaFuncSetAttribute(k_main, cudaFuncAttributeMaxDynamicSharedMemorySize, SMEM_BYTES);

    k_cvt_H <<<NODES * DIM / 256, 256>>>(H);
    k_cvt_W1<<<NEXP * DIM * HDIM / 256, 256>>>(W1);
    k_cvt_W2<<<NEXP * DIM * HDIM / 256, 256>>>(W2);
    k_gate  <<<NODES / 8, 256>>>(H, gate_w, gate_b);
    k_main  <<<NODES / 64, 256, SMEM_BYTES>>>(H, b1, b2, gamma, beta, out);
}

// round 9
// speedup vs baseline: 1.0725x; 1.0725x over previous
#include <cuda_runtime.h>
#include <cuda_bf16.h>
#include <stdint.h>

// Problem dims (fixed by the dataset)
#define NODES 65536
#define DIM   256
#define NEXP  8
#define HDIM  1024
#define NCHUNK 128      // (NEXP*HDIM)/CHW
#define CHW    64       // Hd chunk width

// -------------------- device scratch (static allocation only) --------------------
// All pre-swizzled so TMA bulk copies land in ldmatrix-conflict-free smem layouts.
// Swizzle: within each 16B-granule row, granule' = granule ^ (row & 7).
static __device__ __align__(1024) __nv_bfloat16 g_Hsw [(size_t)NODES * DIM];        // [n][d swz], 512B rows
static __device__ __align__(1024) __nv_bfloat16 g_W1sw[(size_t)NEXP * HDIM * DIM];  // [e][h][d swz], chunk=64 h-rows contiguous (32KB)
static __device__ __align__(1024) __nv_bfloat16 g_W2sw[(size_t)NEXP * HDIM * DIM];  // [e][c][d=256][k=64 swz], 32KB chunks
static __device__ float g_gate[(size_t)NODES * NEXP];

// -------------------- asm helpers --------------------
__device__ __forceinline__ void mma16816(float c[4], const uint32_t a[4], const uint32_t b[2]) {
    asm volatile(
        "mma.sync.aligned.m16n8k16.row.col.f32.bf16.bf16.f32 "
        "{%0,%1,%2,%3}, {%4,%5,%6,%7}, {%8,%9}, {%0,%1,%2,%3};\n"
        : "+f"(c[0]), "+f"(c[1]), "+f"(c[2]), "+f"(c[3])
        : "r"(a[0]), "r"(a[1]), "r"(a[2]), "r"(a[3]), "r"(b[0]), "r"(b[1]));
}
__device__ __forceinline__ void ldm4(uint32_t r[4], uint32_t addr) {
    asm volatile("ldmatrix.sync.aligned.m8n8.x4.shared.b16 {%0,%1,%2,%3}, [%4];"
        : "=r"(r[0]), "=r"(r[1]), "=r"(r[2]), "=r"(r[3]) : "r"(addr));
}
__device__ __forceinline__ void mbar_init(uint32_t bar, uint32_t cnt) {
    asm volatile("mbarrier.init.shared.b64 [%0], %1;" :: "r"(bar), "r"(cnt) : "memory");
}
__device__ __forceinline__ void mbar_expect(uint32_t bar, uint32_t bytes) {
    asm volatile("mbarrier.arrive.expect_tx.shared.b64 _, [%0], %1;" :: "r"(bar), "r"(bytes) : "memory");
}
__device__ __forceinline__ void bulk_g2s(uint32_t dst, const void* src, uint32_t bytes, uint32_t bar) {
    asm volatile("cp.async.bulk.shared::cta.global.mbarrier::complete_tx::bytes [%0], [%1], %2, [%3];"
        :: "r"(dst), "l"(src), "r"(bytes), "r"(bar) : "memory");
}
__device__ __forceinline__ void bar_wait(uint32_t bar, uint32_t ph) {
    asm volatile(
        "{\n\t.reg .pred P;\n"
        "LAB%=:\n\t"
        "mbarrier.try_wait.parity.acquire.cta.shared::cta.b64 P, [%0], %1, 0x989680;\n\t"
        "@!P bra LAB%=;\n\t}"
        :: "r"(bar), "r"(ph) : "memory");
}

// -------------------- prep kernels --------------------
__global__ void k_cvt_H(const float* __restrict__ H) {
    size_t i = (size_t)blockIdx.x * 256 + threadIdx.x;
    int n7 = (int)((i >> 8) & 7);
    int d  = (int)(i & 255);
    int col = ((((d >> 3) ^ n7) << 3) | (d & 7));
    g_Hsw[(i & ~(size_t)255) + col] = __float2bfloat16(H[i]);
}

// W1 [e][d=256][h=1024] -> g_W1sw [e][h][d swz]; tiled transpose
__global__ void k_cvt_W1(const float* __restrict__ W1) {
    __shared__ float t[32][33];
    int e = blockIdx.z, h0 = blockIdx.x * 32, d0 = blockIdx.y * 32;
    int tx = threadIdx.x, ty = threadIdx.y;
#pragma unroll
    for (int j = 0; j < 4; ++j) {
        int d = d0 + ty + j * 8;
        t[ty + j * 8][tx] = W1[((size_t)e * 256 + d) * 1024 + h0 + tx];
    }
    __syncthreads();
#pragma unroll
    for (int j = 0; j < 4; ++j) {
        int h = h0 + ty + j * 8;
        int d = d0 + tx;
        int col = ((((d >> 3) ^ (h & 7)) << 3) | (d & 7));
        g_W1sw[((size_t)e * 1024 + h) * 256 + col] = __float2bfloat16(t[tx][ty + j * 8]);
    }
}

// W2 [e][h=1024][d=256] -> g_W2sw [e][c=h/64][d=256][k=h%64 swz]; tiled transpose
__global__ void k_cvt_W2(const float* __restrict__ W2) {
    __shared__ float t[32][33];
    int e = blockIdx.z, d0 = blockIdx.x * 32, h0 = blockIdx.y * 32;
    int tx = threadIdx.x, ty = threadIdx.y;
#pragma unroll
    for (int j = 0; j < 4; ++j) {
        int h = h0 + ty + j * 8;
        t[ty + j * 8][tx] = W2[((size_t)e * 1024 + h) * 256 + d0 + tx];
    }
    __syncthreads();
#pragma unroll
    for (int j = 0; j < 4; ++j) {
        int d = d0 + ty + j * 8;
        int h = h0 + tx;
        int c = h >> 6, kk = h & 63;
        int col = ((((kk >> 3) ^ (d & 7)) << 3) | (kk & 7));
        g_W2sw[(((size_t)e * 16 + c) * 256 + d) * 64 + col] = __float2bfloat16(t[tx][ty + j * 8]);
    }
}

// Gate: softmax(H @ gate_w + gate_b). One warp per node.
__global__ void k_gate(const float* __restrict__ H, const float* __restrict__ gw,
                       const float* __restrict__ gb) {
    __shared__ float gws[256 * 9];
    int tid = threadIdx.x, lane = tid & 31, wid = tid >> 5;
    for (int i = tid; i < 2048; i += 256) {
        int d = i >> 3, e = i & 7;
        gws[d * 9 + e] = gw[i];
    }
    __syncthreads();
    size_t node = (size_t)blockIdx.x * 8 + wid;
    float acc[8];
#pragma unroll
    for (int e = 0; e < 8; ++e) acc[e] = 0.f;
#pragma unroll
    for (int i = 0; i < 8; ++i) {
        int d = lane + 32 * i;
        float hv = H[node * 256 + d];
#pragma unroll
        for (int e = 0; e < 8; ++e) acc[e] += hv * gws[d * 9 + e];
    }
#pragma unroll
    for (int off = 16; off > 0; off >>= 1)
#pragma unroll
        for (int e = 0; e < 8; ++e) acc[e] += __shfl_xor_sync(0xFFFFFFFFu, acc[e], off);
    float l[8];
#pragma unroll
    for (int e = 0; e < 8; ++e) l[e] = acc[e] + gb[e];
    float m = l[0];
#pragma unroll
    for (int e = 1; e < 8; ++e) m = fmaxf(m, l[e]);
    float ex[8], s = 0.f;
#pragma unroll
    for (int e = 0; e < 8; ++e) { ex[e] = expf(l[e] - m); s += ex[e]; }
    float inv = 1.f / s;
    if (lane < 8) {
        float v = 0.f;
#pragma unroll
        for (int e = 0; e < 8; ++e) if (lane == e) v = ex[e];
        g_gate[node * 8 + lane] = v * inv;
    }
}

// -------------------- main fused kernel --------------------
// 128 nodes/CTA, 512 threads (16 warps: 4m x 4n). 128 chunks of Hd width 64.
// GEMM1: h[128x64] = relu(Hs[128x256] @ W1chunk) + b1, scaled by gate -> hS bf16
// GEMM2: y[128x256] += hS @ W2chunk (fp32 regs, persistent)
// Weights stream via 1D TMA bulk copies, double-buffered with mbarriers.

#define OFF_HS   0          // 128 x 512B (swizzled)         65536
#define OFF_W1   65536      // 2 x 32768 (64 rows x 512B)
#define OFF_W2   131072     // 2 x 32768 (256 rows x 128B)
#define OFF_HSH  196608     // 128 x 144B (72 bf16, padded)  18432
#define OFF_GATE 215040     // 128x8 f32                     4096
#define OFF_B2   219136     // 8x256 f32                     8192
#define OFF_B1   227328     // 2x64 f32                      512
#define OFF_BAR  227840     // 5 mbarriers
#define SMEM_BYTES 227904
#define SX 260              // xS fp32 stride (reuses smem from offset 0)

__global__ void __launch_bounds__(512, 1)
k_main(const float* __restrict__ H, const float* __restrict__ b1g,
       const float* __restrict__ b2g, const float* __restrict__ gamma,
       const float* __restrict__ beta, float* __restrict__ out)
{
    extern __shared__ char smem_raw[];
    const uint32_t smb = (uint32_t)__cvta_generic_to_shared(smem_raw);
    float* gate_s = reinterpret_cast<float*>(smem_raw + OFF_GATE);
    float* b2s    = reinterpret_cast<float*>(smem_raw + OFF_B2);
    float* b1s    = reinterpret_cast<float*>(smem_raw + OFF_B1);
    __nv_bfloat16* hS = reinterpret_cast<__nv_bfloat16*>(smem_raw + OFF_HSH);

    const int tid  = threadIdx.x;
    const int lane = tid & 31, wid = tid >> 5;
    const int wm = wid & 3, wn = wid >> 2;
    const int m0 = wm * 32;
    const int lq = lane >> 2, lr = lane & 3;
    const int l16 = lane & 15;
    const uint32_t hi = (uint32_t)((lane >> 4) << 4);
    const int node0 = blockIdx.x * 128;

    const uint32_t barHs = smb + OFF_BAR;
    const uint32_t barW1 = smb + OFF_BAR + 8;    // +8*buf
    const uint32_t barW2 = smb + OFF_BAR + 24;   // +8*buf

    if (tid == 0) {
#pragma unroll
        for (int i = 0; i < 5; ++i) mbar_init(barHs + i * 8, 1);
    }
    __syncthreads();

    if (tid == 0) {
        mbar_expect(barHs, 65536);
        bulk_g2s(smb + OFF_HS, (const char*)g_Hsw + (size_t)node0 * 512, 65536, barHs);
#pragma unroll
        for (int s = 0; s < 2; ++s) {
            mbar_expect(barW1 + s * 8, 32768);
            bulk_g2s(smb + OFF_W1 + s * 32768, (const char*)g_W1sw + (size_t)s * 32768, 32768, barW1 + s * 8);
            mbar_expect(barW2 + s * 8, 32768);
            bulk_g2s(smb + OFF_W2 + s * 32768, (const char*)g_W2sw + (size_t)s * 32768, 32768, barW2 + s * 8);
        }
    }

    // stage gate, b2, b1 chunk 0
    for (int i = tid; i < 128 * 8; i += 512) gate_s[i] = g_gate[(size_t)node0 * 8 + i];
    for (int i = tid; i < 8 * 256; i += 512) b2s[i] = b2g[i];
    if (tid < CHW) b1s[tid] = b1g[tid];
    __syncthreads();

    float y[2][8][4];
#pragma unroll
    for (int mi = 0; mi < 2; ++mi)
#pragma unroll
        for (int ni = 0; ni < 8; ++ni)
#pragma unroll
            for (int q = 0; q < 4; ++q) y[mi][ni][q] = 0.f;

    bar_wait(barHs, 0);

    // precomputed fragment addresses
    const int rA = m0 + l16;
    const uint32_t swA  = (uint32_t)((rA & 7) << 4);
    const uint32_t paH0 = smb + OFF_HS + rA * 512;
    const uint32_t paH1 = paH0 + 16 * 512;
    const uint32_t pah0 = smb + OFF_HSH + rA * 144;
    const uint32_t pah1 = pah0 + 16 * 144;
    const int rB1 = wn * 16 + l16;
    const uint32_t swB1 = (uint32_t)((rB1 & 7) << 4);
    uint32_t pw2off[4], swB2[4];
#pragma unroll
    for (int p = 0; p < 4; ++p) {
        int r = wn * 64 + p * 16 + l16;
        pw2off[p] = (uint32_t)(r * 128);
        swB2[p] = (uint32_t)((r & 7) << 4);
    }

    for (int cc = 0; cc < NCHUNK; ++cc) {
        const int b = cc & 1;
        const uint32_t ph = (uint32_t)((cc >> 1) & 1);

        bar_wait(barW1 + b * 8, ph);

        // prefetch b1 slice for chunk cc+1 (warps 14-15, 64 threads)
        if (tid >= 448 && cc + 1 < NCHUNK)
            b1s[((cc + 1) & 1) * CHW + (tid - 448)] = b1g[(cc + 1) * CHW + (tid - 448)];

        // ---------------- GEMM1: [128x64] += Hs[128x256] @ W1chunk^T ----------------
        const uint32_t pb1 = smb + OFF_W1 + b * 32768 + rB1 * 512;
        float a1[2][2][4];
#pragma unroll
        for (int mi = 0; mi < 2; ++mi)
#pragma unroll
            for (int ni = 0; ni < 2; ++ni)
#pragma unroll
                for (int q = 0; q < 4; ++q) a1[mi][ni][q] = 0.f;

#pragma unroll
        for (int kk = 0; kk < 16; ++kk) {
            const uint32_t co = (uint32_t)(kk * 32) + hi;
            uint32_t a0[4], a2[4], bb[4];
            ldm4(a0, paH0 + (co ^ swA));
            ldm4(a2, paH1 + (co ^ swA));
            ldm4(bb, pb1 + (co ^ swB1));
            uint32_t bt0[2] = { bb[0], bb[2] };
            uint32_t bt1[2] = { bb[1], bb[3] };
            mma16816(a1[0][0], a0, bt0);
            mma16816(a1[0][1], a0, bt1);
            mma16816(a1[1][0], a2, bt0);
            mma16816(a1[1][1], a2, bt1);
        }

        // epilogue1: +b1, relu, * gate -> hS (bf16)
        const int e = cc >> 4;
#pragma unroll
        for (int mi = 0; mi < 2; ++mi) {
            const int r0 = m0 + mi * 16 + lq, r1 = r0 + 8;
            const float w0 = gate_s[r0 * 8 + e], w1 = gate_s[r1 * 8 + e];
#pragma unroll
            for (int ni = 0; ni < 2; ++ni) {
                const int cl = wn * 16 + ni * 8 + lr * 2;
                const float bb0 = b1s[b * CHW + cl], bb1 = b1s[b * CHW + cl + 1];
                float v00 = fmaxf(a1[mi][ni][0] + bb0, 0.f) * w0;
                float v01 = fmaxf(a1[mi][ni][1] + bb1, 0.f) * w0;
                float v10 = fmaxf(a1[mi][ni][2] + bb0, 0.f) * w1;
                float v11 = fmaxf(a1[mi][ni][3] + bb1, 0.f) * w1;
                *reinterpret_cast<__nv_bfloat162*>(hS + r0 * 72 + cl) = __floats2bfloat162_rn(v00, v01);
                *reinterpret_cast<__nv_bfloat162*>(hS + r1 * 72 + cl) = __floats2bfloat162_rn(v10, v11);
            }
        }
        __syncthreads();   // hS ready; all warps done with W1 buffer

        if (tid == 0 && cc + 2 < NCHUNK) {
            mbar_expect(barW1 + b * 8, 32768);
            bulk_g2s(smb + OFF_W1 + b * 32768, (const char*)g_W1sw + (size_t)(cc + 2) * 32768, 32768, barW1 + b * 8);
        }

        bar_wait(barW2 + b * 8, ph);

        // ---------------- GEMM2: y[128x256] += hS[128x64] @ W2chunk^T ----------------
        const uint32_t pw2 = smb + OFF_W2 + b * 32768;
#pragma unroll
        for (int kk = 0; kk < 4; ++kk) {
            const uint32_t co = (uint32_t)(kk * 32) + hi;
            uint32_t a0[4], a2[4];
            ldm4(a0, pah0 + co);
            ldm4(a2, pah1 + co);
#pragma unroll
            for (int p = 0; p < 4; ++p) {
                uint32_t bb[4];
                ldm4(bb, pw2 + pw2off[p] + (co ^ swB2[p]));
                uint32_t bt0[2] = { bb[0], bb[2] };
                uint32_t bt1[2] = { bb[1], bb[3] };
                mma16816(y[0][2 * p],     a0, bt0);
                mma16816(y[0][2 * p + 1], a0, bt1);
                mma16816(y[1][2 * p],     a2, bt0);
                mma16816(y[1][2 * p + 1], a2, bt1);
            }
        }
        __syncthreads();   // all warps done with W2 buffer + hS

        if (tid == 0 && cc + 2 < NCHUNK) {
            mbar_expect(barW2 + b * 8, 32768);
            bulk_g2s(smb + OFF_W2 + b * 32768, (const char*)g_W2sw + (size_t)(cc + 2) * 32768, 32768, barW2 + b * 8);
        }
    }

    // ---------------- final epilogue: residual + gated b2, LayerNorm ----------------
    float* xS = reinterpret_cast<float*>(smem_raw);   // reuses Hs/W1/W2 regions (all consumed)
#pragma unroll
    for (int mi = 0; mi < 2; ++mi) {
        const int r0 = m0 + mi * 16 + lq, r1 = r0 + 8;
#pragma unroll
        for (int ni = 0; ni < 8; ++ni) {
            const int c2 = wn * 64 + ni * 8 + lr * 2;
            float bx00 = 0.f, bx01 = 0.f, bx10 = 0.f, bx11 = 0.f;
#pragma unroll
            for (int ee = 0; ee < 8; ++ee) {
                const float w0 = gate_s[r0 * 8 + ee];
                const float w1 = gate_s[r1 * 8 + ee];
                const float2 bb = *reinterpret_cast<const float2*>(&b2s[ee * 256 + c2]);
                bx00 += w0 * bb.x; bx01 += w0 * bb.y;
                bx10 += w1 * bb.x; bx11 += w1 * bb.y;
            }
            float2 h0 = *reinterpret_cast<const float2*>(H + (size_t)(node0 + r0) * 256 + c2);
            float2 h1 = *reinterpret_cast<const float2*>(H + (size_t)(node0 + r1) * 256 + c2);
            xS[r0 * SX + c2]     = h0.x + y[mi][ni][0] + bx00;
            xS[r0 * SX + c2 + 1] = h0.y + y[mi][ni][1] + bx01;
            xS[r1 * SX + c2]     = h1.x + y[mi][ni][2] + bx10;
            xS[r1 * SX + c2 + 1] = h1.y + y[mi][ni][3] + bx11;
        }
    }
    __syncthreads();

    // LayerNorm: each of 16 warps handles 8 rows
#pragma unroll
    for (int rr = 0; rr < 8; ++rr) {
        const int r = wid * 8 + rr;
        float xv[8], s = 0.f, s2 = 0.f;
#pragma unroll
        for (int i = 0; i < 8; ++i) {
            xv[i] = xS[r * SX + lane + 32 * i];
            s += xv[i];
            s2 += xv[i] * xv[i];
        }
#pragma unroll
        for (int off = 16; off > 0; off >>= 1) {
            s  += __shfl_xor_sync(0xFFFFFFFFu, s,  off);
            s2 += __shfl_xor_sync(0xFFFFFFFFu, s2, off);
        }
        const float mu  = s * (1.f / 256.f);
        const float var = s2 * (1.f / 256.f) - mu * mu;
        const float rs  = rsqrtf(var + 1e-5f);
#pragma unroll
        for (int i = 0; i < 8; ++i) {
            const int col = lane + 32 * i;
            out[(size_t)(node0 + r) * 256 + col] = (xv[i] - mu) * rs * gamma[col] + beta[col];
        }
    }
}

// -------------------- launch --------------------
extern "C" void kernel_launch(void* const* d_in, const int* in_sizes, int n_in,
                              void* d_out, int out_size) {
    (void)in_sizes; (void)n_in; (void)out_size;
    const float* H      = (const float*)d_in[0];
    const float* gate_w = (const float*)d_in[1];
    const float* gate_b = (const float*)d_in[2];
    const float* W1     = (const float*)d_in[3];
    const float* b1     = (const float*)d_in[4];
    const float* W2     = (const float*)d_in[5];
    const float* b2     = (const float*)d_in[6];
    const float* gamma  = (const float*)d_in[7];
    const float* beta   = (const float*)d_in[8];
    float* out = (float*)d_out;

    cudaFuncSetAttribute(k_main, cudaFuncAttributeMaxDynamicSharedMemorySize, SMEM_BYTES);

    k_cvt_H <<<NODES * DIM / 256, 256>>>(H);
    k_cvt_W1<<<dim3(32, 8, 8), dim3(32, 8)>>>(W1);
    k_cvt_W2<<<dim3(8, 32, 8), dim3(32, 8)>>>(W2);
    k_gate  <<<NODES / 8, 256>>>(H, gate_w, gate_b);
    k_main  <<<NODES / 128, 512, SMEM_BYTES>>>(H, b1, b2, gamma, beta, out);
}

// round 10
// speedup vs baseline: 1.0735x; 1.0010x over previous
#include <cuda_runtime.h>
#include <cuda_bf16.h>
#include <stdint.h>

// Problem dims (fixed by the dataset)
#define NODES 65536
#define DIM   256
#define NEXP  8
#define HDIM  1024
#define NCHUNK 128      // (NEXP*HDIM)/CHW
#define CHW    64       // Hd chunk width

// -------------------- device scratch (static allocation only) --------------------
// All pre-swizzled so TMA bulk copies land in ldmatrix-conflict-free smem layouts.
// Swizzle: within each 16B-granule row, granule' = granule ^ (row & 7).
static __device__ __align__(1024) __nv_bfloat16 g_Hsw [(size_t)NODES * DIM];        // [n][d swz], 512B rows
static __device__ __align__(1024) __nv_bfloat16 g_W1sw[(size_t)NEXP * HDIM * DIM];  // [e][h][d swz], chunk=64 h-rows contiguous (32KB)
static __device__ __align__(1024) __nv_bfloat16 g_W2sw[(size_t)NEXP * HDIM * DIM];  // [e][c][d=256][k=64 swz], 32KB chunks
static __device__ float g_gate[(size_t)NODES * NEXP];

// -------------------- asm helpers --------------------
__device__ __forceinline__ void mma16816(float c[4], const uint32_t a[4], const uint32_t b[2]) {
    asm volatile(
        "mma.sync.aligned.m16n8k16.row.col.f32.bf16.bf16.f32 "
        "{%0,%1,%2,%3}, {%4,%5,%6,%7}, {%8,%9}, {%0,%1,%2,%3};\n"
        : "+f"(c[0]), "+f"(c[1]), "+f"(c[2]), "+f"(c[3])
        : "r"(a[0]), "r"(a[1]), "r"(a[2]), "r"(a[3]), "r"(b[0]), "r"(b[1]));
}
__device__ __forceinline__ void ldm4(uint32_t r[4], uint32_t addr) {
    asm volatile("ldmatrix.sync.aligned.m8n8.x4.shared.b16 {%0,%1,%2,%3}, [%4];"
        : "=r"(r[0]), "=r"(r[1]), "=r"(r[2]), "=r"(r[3]) : "r"(addr));
}
__device__ __forceinline__ void mbar_init(uint32_t bar, uint32_t cnt) {
    asm volatile("mbarrier.init.shared.b64 [%0], %1;" :: "r"(bar), "r"(cnt) : "memory");
}
__device__ __forceinline__ void mbar_expect(uint32_t bar, uint32_t bytes) {
    asm volatile("mbarrier.arrive.expect_tx.shared.b64 _, [%0], %1;" :: "r"(bar), "r"(bytes) : "memory");
}
__device__ __forceinline__ void bulk_g2s(uint32_t dst, const void* src, uint32_t bytes, uint32_t bar) {
    asm volatile("cp.async.bulk.shared::cta.global.mbarrier::complete_tx::bytes [%0], [%1], %2, [%3];"
        :: "r"(dst), "l"(src), "r"(bytes), "r"(bar) : "memory");
}
__device__ __forceinline__ void bar_wait(uint32_t bar, uint32_t ph) {
    asm volatile(
        "{\n\t.reg .pred P;\n"
        "LAB%=:\n\t"
        "mbarrier.try_wait.parity.acquire.cta.shared::cta.b64 P, [%0], %1, 0x989680;\n\t"
        "@!P bra LAB%=;\n\t}"
        :: "r"(bar), "r"(ph) : "memory");
}

// -------------------- prep kernels --------------------
__global__ void k_cvt_H(const float* __restrict__ H) {
    size_t i = (size_t)blockIdx.x * 256 + threadIdx.x;
    int n7 = (int)((i >> 8) & 7);
    int d  = (int)(i & 255);
    int col = ((((d >> 3) ^ n7) << 3) | (d & 7));
    g_Hsw[(i & ~(size_t)255) + col] = __float2bfloat16(H[i]);
}

// W1 [e][d=256][h=1024] -> g_W1sw [e][h][d swz]; tiled transpose
__global__ void k_cvt_W1(const float* __restrict__ W1) {
    __shared__ float t[32][33];
    int e = blockIdx.z, h0 = blockIdx.x * 32, d0 = blockIdx.y * 32;
    int tx = threadIdx.x, ty = threadIdx.y;
#pragma unroll
    for (int j = 0; j < 4; ++j) {
        int d = d0 + ty + j * 8;
        t[ty + j * 8][tx] = W1[((size_t)e * 256 + d) * 1024 + h0 + tx];
    }
    __syncthreads();
#pragma unroll
    for (int j = 0; j < 4; ++j) {
        int h = h0 + ty + j * 8;
        int d = d0 + tx;
        int col = ((((d >> 3) ^ (h & 7)) << 3) | (d & 7));
        g_W1sw[((size_t)e * 1024 + h) * 256 + col] = __float2bfloat16(t[tx][ty + j * 8]);
    }
}

// W2 [e][h=1024][d=256] -> g_W2sw [e][c=h/64][d=256][k=h%64 swz]; tiled transpose
__global__ void k_cvt_W2(const float* __restrict__ W2) {
    __shared__ float t[32][33];
    int e = blockIdx.z, d0 = blockIdx.x * 32, h0 = blockIdx.y * 32;
    int tx = threadIdx.x, ty = threadIdx.y;
#pragma unroll
    for (int j = 0; j < 4; ++j) {
        int h = h0 + ty + j * 8;
        t[ty + j * 8][tx] = W2[((size_t)e * 1024 + h) * 256 + d0 + tx];
    }
    __syncthreads();
#pragma unroll
    for (int j = 0; j < 4; ++j) {
        int d = d0 + ty + j * 8;
        int h = h0 + tx;
        int c = h >> 6, kk = h & 63;
        int col = ((((kk >> 3) ^ (d & 7)) << 3) | (kk & 7));
        g_W2sw[(((size_t)e * 16 + c) * 256 + d) * 64 + col] = __float2bfloat16(t[tx][ty + j * 8]);
    }
}

// Gate: softmax(H @ gate_w + gate_b). One warp per node.
__global__ void k_gate(const float* __restrict__ H, const float* __restrict__ gw,
                       const float* __restrict__ gb) {
    __shared__ float gws[256 * 9];
    int tid = threadIdx.x, lane = tid & 31, wid = tid >> 5;
    for (int i = tid; i < 2048; i += 256) {
        int d = i >> 3, e = i & 7;
        gws[d * 9 + e] = gw[i];
    }
    __syncthreads();
    size_t node = (size_t)blockIdx.x * 8 + wid;
    float acc[8];
#pragma unroll
    for (int e = 0; e < 8; ++e) acc[e] = 0.f;
#pragma unroll
    for (int i = 0; i < 8; ++i) {
        int d = lane + 32 * i;
        float hv = H[node * 256 + d];
#pragma unroll
        for (int e = 0; e < 8; ++e) acc[e] += hv * gws[d * 9 + e];
    }
#pragma unroll
    for (int off = 16; off > 0; off >>= 1)
#pragma unroll
        for (int e = 0; e < 8; ++e) acc[e] += __shfl_xor_sync(0xFFFFFFFFu, acc[e], off);
    float l[8];
#pragma unroll
    for (int e = 0; e < 8; ++e) l[e] = acc[e] + gb[e];
    float m = l[0];
#pragma unroll
    for (int e = 1; e < 8; ++e) m = fmaxf(m, l[e]);
    float ex[8], s = 0.f;
#pragma unroll
    for (int e = 0; e < 8; ++e) { ex[e] = expf(l[e] - m); s += ex[e]; }
    float inv = 1.f / s;
    if (lane < 8) {
        float v = 0.f;
#pragma unroll
        for (int e = 0; e < 8; ++e) if (lane == e) v = ex[e];
        g_gate[node * 8 + lane] = v * inv;
    }
}

// -------------------- main fused kernel --------------------
// 128 nodes/CTA, 512 threads (16 warps: 4m x 4n). 128 chunks of Hd width 64.
// GEMM1: h[128x64] = relu(Hs[128x256] @ W1chunk) + b1, scaled by gate -> hS bf16
// GEMM2: y[128x256] += hS @ W2chunk (fp32 regs, persistent)
// Weights stream via 1D TMA bulk copies, double-buffered with mbarriers.

#define OFF_HS   0          // 128 x 512B (swizzled)         65536
#define OFF_W1   65536      // 2 x 32768 (64 rows x 512B)
#define OFF_W2   131072     // 2 x 32768 (256 rows x 128B)
#define OFF_HSH  196608     // 128 x 144B (72 bf16, padded)  18432
#define OFF_GATE 215040     // 128x8 f32                     4096
#define OFF_B2   219136     // 8x256 f32                     8192
#define OFF_B1   227328     // 2x64 f32                      512
#define OFF_BAR  227840     // 5 mbarriers
#define SMEM_BYTES 227904
#define SX 260              // xS fp32 stride (reuses smem from offset 0)

__global__ void __launch_bounds__(512, 1)
k_main(const float* __restrict__ H, const float* __restrict__ b1g,
       const float* __restrict__ b2g, const float* __restrict__ gamma,
       const float* __restrict__ beta, float* __restrict__ out)
{
    extern __shared__ char smem_raw[];
    const uint32_t smb = (uint32_t)__cvta_generic_to_shared(smem_raw);
    float* gate_s = reinterpret_cast<float*>(smem_raw + OFF_GATE);
    float* b2s    = reinterpret_cast<float*>(smem_raw + OFF_B2);
    float* b1s    = reinterpret_cast<float*>(smem_raw + OFF_B1);
    __nv_bfloat16* hS = reinterpret_cast<__nv_bfloat16*>(smem_raw + OFF_HSH);

    const int tid  = threadIdx.x;
    const int lane = tid & 31, wid = tid >> 5;
    const int wm = wid & 3, wn = wid >> 2;
    const int m0 = wm * 32;
    const int lq = lane >> 2, lr = lane & 3;
    const int l16 = lane & 15;
    const uint32_t hi = (uint32_t)((lane >> 4) << 4);
    const int node0 = blockIdx.x * 128;

    const uint32_t barHs = smb + OFF_BAR;
    const uint32_t barW1 = smb + OFF_BAR + 8;    // +8*buf
    const uint32_t barW2 = smb + OFF_BAR + 24;   // +8*buf

    if (tid == 0) {
#pragma unroll
        for (int i = 0; i < 5; ++i) mbar_init(barHs + i * 8, 1);
    }
    __syncthreads();

    if (tid == 0) {
        mbar_expect(barHs, 65536);
        bulk_g2s(smb + OFF_HS, (const char*)g_Hsw + (size_t)node0 * 512, 65536, barHs);
#pragma unroll
        for (int s = 0; s < 2; ++s) {
            mbar_expect(barW1 + s * 8, 32768);
            bulk_g2s(smb + OFF_W1 + s * 32768, (const char*)g_W1sw + (size_t)s * 32768, 32768, barW1 + s * 8);
            mbar_expect(barW2 + s * 8, 32768);
            bulk_g2s(smb + OFF_W2 + s * 32768, (const char*)g_W2sw + (size_t)s * 32768, 32768, barW2 + s * 8);
        }
    }

    // stage gate, b2, b1 chunk 0
    for (int i = tid; i < 128 * 8; i += 512) gate_s[i] = g_gate[(size_t)node0 * 8 + i];
    for (int i = tid; i < 8 * 256; i += 512) b2s[i] = b2g[i];
    if (tid < CHW) b1s[tid] = b1g[tid];
    __syncthreads();

    float y[2][8][4];
#pragma unroll
    for (int mi = 0; mi < 2; ++mi)
#pragma unroll
        for (int ni = 0; ni < 8; ++ni)
#pragma unroll
            for (int q = 0; q < 4; ++q) y[mi][ni][q] = 0.f;

    bar_wait(barHs, 0);

    // precomputed fragment addresses
    const int rA = m0 + l16;
    const uint32_t swA  = (uint32_t)((rA & 7) << 4);
    const uint32_t paH0 = smb + OFF_HS + rA * 512;
    const uint32_t paH1 = paH0 + 16 * 512;
    const uint32_t pah0 = smb + OFF_HSH + rA * 144;
    const uint32_t pah1 = pah0 + 16 * 144;
    const int rB1 = wn * 16 + l16;
    const uint32_t swB1 = (uint32_t)((rB1 & 7) << 4);
    uint32_t pw2off[4], swB2[4];
#pragma unroll
    for (int p = 0; p < 4; ++p) {
        int r = wn * 64 + p * 16 + l16;
        pw2off[p] = (uint32_t)(r * 128);
        swB2[p] = (uint32_t)((r & 7) << 4);
    }

    for (int cc = 0; cc < NCHUNK; ++cc) {
        const int b = cc & 1;
        const uint32_t ph = (uint32_t)((cc >> 1) & 1);

        bar_wait(barW1 + b * 8, ph);

        // prefetch b1 slice for chunk cc+1 (warps 14-15, 64 threads)
        if (tid >= 448 && cc + 1 < NCHUNK)
            b1s[((cc + 1) & 1) * CHW + (tid - 448)] = b1g[(cc + 1) * CHW + (tid - 448)];

        // ---------------- GEMM1: [128x64] += Hs[128x256] @ W1chunk^T ----------------
        const uint32_t pb1 = smb + OFF_W1 + b * 32768 + rB1 * 512;
        float a1[2][2][4];
#pragma unroll
        for (int mi = 0; mi < 2; ++mi)
#pragma unroll
            for (int ni = 0; ni < 2; ++ni)
#pragma unroll
                for (int q = 0; q < 4; ++q) a1[mi][ni][q] = 0.f;

#pragma unroll
        for (int kk = 0; kk < 16; ++kk) {
            const uint32_t co = (uint32_t)(kk * 32) + hi;
            uint32_t a0[4], a2[4], bb[4];
            ldm4(a0, paH0 + (co ^ swA));
            ldm4(a2, paH1 + (co ^ swA));
            ldm4(bb, pb1 + (co ^ swB1));
            uint32_t bt0[2] = { bb[0], bb[2] };
            uint32_t bt1[2] = { bb[1], bb[3] };
            mma16816(a1[0][0], a0, bt0);
            mma16816(a1[0][1], a0, bt1);
            mma16816(a1[1][0], a2, bt0);
            mma16816(a1[1][1], a2, bt1);
        }

        // epilogue1: +b1, relu, * gate -> hS (bf16)
        const int e = cc >> 4;
#pragma unroll
        for (int mi = 0; mi < 2; ++mi) {
            const int r0 = m0 + mi * 16 + lq, r1 = r0 + 8;
            const float w0 = gate_s[r0 * 8 + e], w1 = gate_s[r1 * 8 + e];
#pragma unroll
            for (int ni = 0; ni < 2; ++ni) {
                const int cl = wn * 16 + ni * 8 + lr * 2;
                const float bb0 = b1s[b * CHW + cl], bb1 = b1s[b * CHW + cl + 1];
                float v00 = fmaxf(a1[mi][ni][0] + bb0, 0.f) * w0;
                float v01 = fmaxf(a1[mi][ni][1] + bb1, 0.f) * w0;
                float v10 = fmaxf(a1[mi][ni][2] + bb0, 0.f) * w1;
                float v11 = fmaxf(a1[mi][ni][3] + bb1, 0.f) * w1;
                *reinterpret_cast<__nv_bfloat162*>(hS + r0 * 72 + cl) = __floats2bfloat162_rn(v00, v01);
                *reinterpret_cast<__nv_bfloat162*>(hS + r1 * 72 + cl) = __floats2bfloat162_rn(v10, v11);
            }
        }
        __syncthreads();   // hS ready; all warps done with W1 buffer

        if (tid == 0 && cc + 2 < NCHUNK) {
            mbar_expect(barW1 + b * 8, 32768);
            bulk_g2s(smb + OFF_W1 + b * 32768, (const char*)g_W1sw + (size_t)(cc + 2) * 32768, 32768, barW1 + b * 8);
        }

        bar_wait(barW2 + b * 8, ph);

        // ---------------- GEMM2: y[128x256] += hS[128x64] @ W2chunk^T ----------------
        const uint32_t pw2 = smb + OFF_W2 + b * 32768;
#pragma unroll
        for (int kk = 0; kk < 4; ++kk) {
            const uint32_t co = (uint32_t)(kk * 32) + hi;
            uint32_t a0[4], a2[4];
            ldm4(a0, pah0 + co);
            ldm4(a2, pah1 + co);
#pragma unroll
            for (int p = 0; p < 4; ++p) {
                uint32_t bb[4];
                ldm4(bb, pw2 + pw2off[p] + (co ^ swB2[p]));
                uint32_t bt0[2] = { bb[0], bb[2] };
                uint32_t bt1[2] = { bb[1], bb[3] };
                mma16816(y[0][2 * p],     a0, bt0);
                mma16816(y[0][2 * p + 1], a0, bt1);
                mma16816(y[1][2 * p],     a2, bt0);
                mma16816(y[1][2 * p + 1], a2, bt1);
            }
        }
        __syncthreads();   // all warps done with W2 buffer + hS

        if (tid == 0 && cc + 2 < NCHUNK) {
            mbar_expect(barW2 + b * 8, 32768);
            bulk_g2s(smb + OFF_W2 + b * 32768, (const char*)g_W2sw + (size_t)(cc + 2) * 32768, 32768, barW2 + b * 8);
        }
    }

    // ---------------- final epilogue: residual + gated b2, LayerNorm ----------------
    float* xS = reinterpret_cast<float*>(smem_raw);   // reuses Hs/W1/W2 regions (all consumed)
#pragma unroll
    for (int mi = 0; mi < 2; ++mi) {
        const int r0 = m0 + mi * 16 + lq, r1 = r0 + 8;
#pragma unroll
        for (int ni = 0; ni < 8; ++ni) {
            const int c2 = wn * 64 + ni * 8 + lr * 2;
            float bx00 = 0.f, bx01 = 0.f, bx10 = 0.f, bx11 = 0.f;
#pragma unroll
            for (int ee = 0; ee < 8; ++ee) {
                const float w0 = gate_s[r0 * 8 + ee];
                const float w1 = gate_s[r1 * 8 + ee];
                const float2 bb = *reinterpret_cast<const float2*>(&b2s[ee * 256 + c2]);
                bx00 += w0 * bb.x; bx01 += w0 * bb.y;
                bx10 += w1 * bb.x; bx11 += w1 * bb.y;
            }
            float2 h0 = *reinterpret_cast<const float2*>(H + (size_t)(node0 + r0) * 256 + c2);
            float2 h1 = *reinterpret_cast<const float2*>(H + (size_t)(node0 + r1) * 256 + c2);
            xS[r0 * SX + c2]     = h0.x + y[mi][ni][0] + bx00;
            xS[r0 * SX + c2 + 1] = h0.y + y[mi][ni][1] + bx01;
            xS[r1 * SX + c2]     = h1.x + y[mi][ni][2] + bx10;
            xS[r1 * SX + c2 + 1] = h1.y + y[mi][ni][3] + bx11;
        }
    }
    __syncthreads();

    // LayerNorm: each of 16 warps handles 8 rows
#pragma unroll
    for (int rr = 0; rr < 8; ++rr) {
        const int r = wid * 8 + rr;
        float xv[8], s = 0.f, s2 = 0.f;
#pragma unroll
        for (int i = 0; i < 8; ++i) {
            xv[i] = xS[r * SX + lane + 32 * i];
            s += xv[i];
            s2 += xv[i] * xv[i];
        }
#pragma unroll
        for (int off = 16; off > 0; off >>= 1) {
            s  += __shfl_xor_sync(0xFFFFFFFFu, s,  off);
            s2 += __shfl_xor_sync(0xFFFFFFFFu, s2, off);
        }
        const float mu  = s * (1.f / 256.f);
        const float var = s2 * (1.f / 256.f) - mu * mu;
        const float rs  = rsqrtf(var + 1e-5f);
#pragma unroll
        for (int i = 0; i < 8; ++i) {
            const int col = lane + 32 * i;
            out[(size_t)(node0 + r) * 256 + col] = (xv[i] - mu) * rs * gamma[col] + beta[col];
        }
    }
}

// -------------------- launch --------------------
extern "C" void kernel_launch(void* const* d_in, const int* in_sizes, int n_in,
                              void* d_out, int out_size) {
    (void)in_sizes; (void)n_in; (void)out_size;
    const float* H      = (const float*)d_in[0];
    const float* gate_w = (const float*)d_in[1];
    const float* gate_b = (const float*)d_in[2];
    const float* W1     = (const float*)d_in[3];
    const float* b1     = (const float*)d_in[4];
    const float* W2     = (const float*)d_in[5];
    const float* b2     = (const float*)d_in[6];
    const float* gamma  = (const float*)d_in[7];
    const float* beta   = (const float*)d_in[8];
    float* out = (float*)d_out;

    cudaFuncSetAttribute(k_main, cudaFuncAttributeMaxDynamicSharedMemorySize, SMEM_BYTES);

    k_cvt_H <<<NODES * DIM / 256, 256>>>(H);
    k_cvt_W1<<<dim3(32, 8, 8), dim3(32, 8)>>>(W1);
    k_cvt_W2<<<dim3(8, 32, 8), dim3(32, 8)>>>(W2);
    k_gate  <<<NODES / 8, 256>>>(H, gate_w, gate_b);
    k_main  <<<NODES / 128, 512, SMEM_BYTES>>>(H, b1, b2, gamma, beta, out);
}